// round 7
// baseline (speedup 1.0000x reference)
#include <cuda_runtime.h>
#include <cuda_bf16.h>

// yoloLoss: pred/target [B=4096, S=14, S=14, 30] fp32 -> scalar loss.
// HBM-bound: 192.6 MB read. Coalesced float4 staging of 128 cells/block into
// SMEM, per-thread cell math, DOUBLE accumulation, tiny finalize kernel.
//
// CRITICAL: the IoU chain feeding argmax uses non-contractible IEEE intrinsics
// (__fadd_rn/__fsub_rn/__fmul_rn/__fdiv_rn) in the reference's exact op order.
// Degenerate (clamped) boxes make iou a +/-1ulp residue around 0, so FMA
// contraction flips argmax decisions vs XLA -> 1.4e-3 systematic error.
// (Resubmission of Round-3 kernel: previous round died on container infra.)

#define SDIM 14
#define CPB 128          // cells per block
#define NTHREADS 128

__device__ double g_acc;

__global__ void zero_acc_kernel() { g_acc = 0.0; }

__global__ void finalize_kernel(float* out, int n, double inv_batch) {
    int i = threadIdx.x;
    if (i < n) out[i] = (float)(g_acc * inv_batch);
}

__device__ __forceinline__ float smooth_l1(float d) {
    float ad = fabsf(d);
    return ad < 1.0f ? 0.5f * d * d : ad - 0.5f;
}

__global__ void __launch_bounds__(NTHREADS) yolo_loss_kernel(
    const float* __restrict__ pred,
    const float* __restrict__ target,
    int n_cells)
{
    __shared__ float sp[CPB * 30];
    __shared__ float st[CPB * 30];
    __shared__ double warp_sums[NTHREADS / 32];

    const int tid = threadIdx.x;
    const long long base = (long long)blockIdx.x * (CPB * 30);
    const long long total = (long long)n_cells * 30;

    // Coalesced staging: 960 float4 per array per block.
    const float4* gp = reinterpret_cast<const float4*>(pred + base);
    const float4* gt = reinterpret_cast<const float4*>(target + base);
    float4* s4p = reinterpret_cast<float4*>(sp);
    float4* s4t = reinterpret_cast<float4*>(st);
    long long rem4 = (total - base) / 4;
    int n4 = (rem4 < (CPB * 30 / 4)) ? (int)rem4 : (CPB * 30 / 4);
    for (int idx = tid; idx < n4; idx += NTHREADS) {
        s4p[idx] = gp[idx];
        s4t[idx] = gt[idx];
    }
    __syncthreads();

    double loss = 0.0;
    const int cell = blockIdx.x * CPB + tid;
    if (cell < n_cells) {
        const float* p = sp + tid * 30;
        const float* t = st + tid * 30;

        const int cell_in_img = cell % (SDIM * SDIM);
        const float gi = (float)(cell_in_img % SDIM);   // varies along axis 2
        const float gj = (float)(cell_in_img / SDIM);   // varies along axis 1
        const float STEPF = 1.0f / 14.0f;               // f32-rounded 1/14, same as XLA

        // IoU of pred box k vs target box k, bit-exact to XLA op-by-op:
        //   x = max((bx + g) * STEP - bw * 0.5, 0);  w = max(bw, 0)
        //   iw = max(w1 + w2 - (max(x1+w1, x2+w2) - min(x1, x2)), 0)
        //   iou = inter / (union + 1e-6)
        float iou[2];
        #pragma unroll
        for (int k = 0; k < 2; k++) {
            const float pbx = p[5*k+0], pby = p[5*k+1], pbw = p[5*k+2], pbh = p[5*k+3];
            const float tbx = t[5*k+0], tby = t[5*k+1], tbw = t[5*k+2], tbh = t[5*k+3];

            float px = fmaxf(__fsub_rn(__fmul_rn(__fadd_rn(pbx, gi), STEPF),
                                       __fmul_rn(pbw, 0.5f)), 0.0f);
            float py = fmaxf(__fsub_rn(__fmul_rn(__fadd_rn(pby, gj), STEPF),
                                       __fmul_rn(pbh, 0.5f)), 0.0f);
            float pw = fmaxf(pbw, 0.0f);
            float ph = fmaxf(pbh, 0.0f);
            float tx = fmaxf(__fsub_rn(__fmul_rn(__fadd_rn(tbx, gi), STEPF),
                                       __fmul_rn(tbw, 0.5f)), 0.0f);
            float ty = fmaxf(__fsub_rn(__fmul_rn(__fadd_rn(tby, gj), STEPF),
                                       __fmul_rn(tbh, 0.5f)), 0.0f);
            float tw = fmaxf(tbw, 0.0f);
            float th = fmaxf(tbh, 0.0f);

            float iw = fmaxf(__fsub_rn(__fadd_rn(pw, tw),
                                       __fsub_rn(fmaxf(__fadd_rn(px, pw), __fadd_rn(tx, tw)),
                                                 fminf(px, tx))), 0.0f);
            float ih = fmaxf(__fsub_rn(__fadd_rn(ph, th),
                                       __fsub_rn(fmaxf(__fadd_rn(py, ph), __fadd_rn(ty, th)),
                                                 fminf(py, ty))), 0.0f);
            float inter = __fmul_rn(iw, ih);
            float uni = __fsub_rn(__fadd_rn(__fmul_rn(pw, ph), __fmul_rn(tw, th)), inter);
            iou[k] = __fdiv_rn(inter, __fadd_rn(uni, 1e-6f));
        }

        const bool ob0 = t[4] > 0.0f;
        const bool ob1 = t[9] > 0.0f;
        const bool sig = ob1;                         // sig_mask = obj_mask[..., 1]
        // jnp.argmax: first max wins -> pick 1 only if strictly greater
        const int max_i = (iou[1] > iou[0]) ? 1 : 0;
        const bool om0 = sig ? (ob0 && (max_i == 0)) : ob0;
        const bool om1 = sig ? (max_i == 1) : ob1;    // ob1 is true when sig

        // Confidence terms
        float d0 = p[4] - t[4]; d0 *= d0;
        float d1 = p[9] - t[9]; d1 *= d1;
        float obj_loss   = (om0 ? d0 : 0.0f) + (om1 ? d1 : 0.0f);
        float noobj_loss = (om0 ? 0.0f : d0) + (om1 ? 0.0f : d1);

        // Coord terms (smooth-L1 on raw xy; on sqrt(max(wh,1e-6)))
        float coord = 0.0f;
        if (om0) {
            coord += smooth_l1(p[0] - t[0]) + smooth_l1(p[1] - t[1]);
            coord += smooth_l1(__fsqrt_rn(fmaxf(p[2], 1e-6f)) - __fsqrt_rn(fmaxf(t[2], 1e-6f)));
            coord += smooth_l1(__fsqrt_rn(fmaxf(p[3], 1e-6f)) - __fsqrt_rn(fmaxf(t[3], 1e-6f)));
        }
        if (om1) {
            coord += smooth_l1(p[5] - t[5]) + smooth_l1(p[6] - t[6]);
            coord += smooth_l1(__fsqrt_rn(fmaxf(p[7], 1e-6f)) - __fsqrt_rn(fmaxf(t[7], 1e-6f)));
            coord += smooth_l1(__fsqrt_rn(fmaxf(p[8], 1e-6f)) - __fsqrt_rn(fmaxf(t[8], 1e-6f)));
        }

        // Class loss: NLL of log_softmax over 20 classes at argmax(target_cls).
        float cls = 0.0f;
        if (sig) {
            float m = p[10];
            #pragma unroll
            for (int c = 1; c < 20; c++) m = fmaxf(m, p[10 + c]);
            float s = 0.0f;
            #pragma unroll
            for (int c = 0; c < 20; c++) s += expf(p[10 + c] - m);
            float bm = t[10];
            int bi = 0;
            #pragma unroll
            for (int c = 1; c < 20; c++) {
                if (t[10 + c] > bm) { bm = t[10 + c]; bi = c; }
            }
            cls = m + logf(s) - p[10 + bi];
        }

        loss = 3.0 * (double)coord + 1.0 * (double)obj_loss
             + 0.3 * (double)noobj_loss + 1.5 * (double)cls;
    }

    // Block reduction in double: warp shuffle, then cross-warp via SMEM.
    #pragma unroll
    for (int off = 16; off > 0; off >>= 1)
        loss += __shfl_down_sync(0xFFFFFFFFu, loss, off);
    if ((tid & 31) == 0) warp_sums[tid >> 5] = loss;
    __syncthreads();
    if (tid == 0) {
        double s = warp_sums[0];
        #pragma unroll
        for (int w = 1; w < NTHREADS / 32; w++) s += warp_sums[w];
        atomicAdd(&g_acc, s);
    }
}

extern "C" void kernel_launch(void* const* d_in, const int* in_sizes, int n_in,
                              void* d_out, int out_size) {
    const float* pred   = (const float*)d_in[0];
    const float* target = (const float*)d_in[1];
    float* out = (float*)d_out;

    const int n_cells = in_sizes[0] / 30;
    const int batch = n_cells / (SDIM * SDIM);
    const double inv_batch = 1.0 / (double)batch;
    const int blocks = (n_cells + CPB - 1) / CPB;

    zero_acc_kernel<<<1, 1>>>();
    yolo_loss_kernel<<<blocks, NTHREADS>>>(pred, target, n_cells);
    finalize_kernel<<<1, 32>>>(out, out_size, inv_batch);
}